// round 1
// baseline (speedup 1.0000x reference)
#include <cuda_runtime.h>
#include <math.h>

#define QN 16
#define IN 64
#define PB 128
#define JN 256
#define DN 768

// Scratch (device globals: no allocation, allowed by harness rules)
__device__ float g_qn[QN * IN * DN];        // ~3 MB normalized q
__device__ float g_pn[PB * JN * DN];        // ~100 MB normalized p
__device__ float g_scores[QN * PB];
__device__ float g_mv[QN * PB];

// ---------------------------------------------------------------------------
// Row L2-normalize: one block per row of 768, 256 threads
// ---------------------------------------------------------------------------
__device__ __forceinline__ void normalize_row(const float* __restrict__ xr,
                                              float* __restrict__ yr) {
    int tid = threadIdx.x;
    float v0 = xr[tid], v1 = xr[tid + 256], v2 = xr[tid + 512];
    float ss = v0 * v0 + v1 * v1 + v2 * v2;
#pragma unroll
    for (int o = 16; o; o >>= 1) ss += __shfl_xor_sync(0xffffffffu, ss, o);
    __shared__ float red[8];
    __shared__ float inv;
    if ((tid & 31) == 0) red[tid >> 5] = ss;
    __syncthreads();
    if (tid == 0) {
        float t = 0.f;
#pragma unroll
        for (int i = 0; i < 8; i++) t += red[i];
        float n = sqrtf(t);
        inv = 1.0f / fmaxf(n, 1e-12f);
    }
    __syncthreads();
    float iv = inv;
    yr[tid] = v0 * iv;
    yr[tid + 256] = v1 * iv;
    yr[tid + 512] = v2 * iv;
}

__global__ void norm_q_kernel(const float* __restrict__ x) {
    size_t row = blockIdx.x;
    normalize_row(x + row * DN, g_qn + row * DN);
}

__global__ void norm_p_kernel(const float* __restrict__ x) {
    size_t row = blockIdx.x;
    normalize_row(x + row * DN, g_pn + row * DN);
}

// ---------------------------------------------------------------------------
// scores[q][p] = dot(q_hidden[q,0,:], p_hidden[p,0,:])
// ---------------------------------------------------------------------------
__global__ void scores_kernel(const float* __restrict__ qh,
                              const float* __restrict__ ph) {
    int q = blockIdx.x;
    int p = threadIdx.x;  // 128 threads
    __shared__ float qs[DN];
    for (int k = p; k < DN; k += PB) qs[k] = qh[(size_t)q * IN * DN + k];
    __syncthreads();
    const float* pr = ph + (size_t)p * JN * DN;  // row j=0 of page p
    float s = 0.f;
    for (int k = 0; k < DN; k++) s = fmaf(qs[k], pr[k], s);
    g_scores[q * PB + p] = s;
}

// ---------------------------------------------------------------------------
// mv_scores[q][p] = max_{i,j} qn[q,i,:] . pn[p,j,:]
// Register-blocked GEMM tile 64(i) x 256(j), K=768, 8x8 microtile per thread.
// ---------------------------------------------------------------------------
__global__ __launch_bounds__(256) void mv_kernel() {
    const int p = blockIdx.x;
    const int q = blockIdx.y;
    __shared__ float As[32][68];    // [k][i], padded (stride%4==0 for float4)
    __shared__ float Bs[32][260];   // [k][j], padded

    const float* Aq = g_qn + (size_t)q * IN * DN;
    const float* Bp = g_pn + (size_t)p * JN * DN;
    const int tid = threadIdx.x;
    const int ti = tid >> 5;   // warp id -> i block (8 rows)
    const int tj = tid & 31;   // lane -> j block (8 cols)

    float acc[8][8];
#pragma unroll
    for (int u = 0; u < 8; u++)
#pragma unroll
        for (int v = 0; v < 8; v++) acc[u][v] = 0.f;

    for (int k0 = 0; k0 < DN; k0 += 32) {
        // A chunk: 64 rows x 32 k = 512 float4, 2 per thread (transpose store)
#pragma unroll
        for (int r = 0; r < 2; r++) {
            int idx = tid * 2 + r;
            int i = idx >> 3;
            int kq = (idx & 7) << 2;
            float4 v = *(const float4*)(Aq + (size_t)i * DN + k0 + kq);
            As[kq + 0][i] = v.x;
            As[kq + 1][i] = v.y;
            As[kq + 2][i] = v.z;
            As[kq + 3][i] = v.w;
        }
        // B chunk: 256 rows x 32 k = 2048 float4, 8 per thread
#pragma unroll
        for (int r = 0; r < 8; r++) {
            int idx = tid + 256 * r;
            int j = idx >> 3;
            int kq = (idx & 7) << 2;
            float4 v = *(const float4*)(Bp + (size_t)j * DN + k0 + kq);
            Bs[kq + 0][j] = v.x;
            Bs[kq + 1][j] = v.y;
            Bs[kq + 2][j] = v.z;
            Bs[kq + 3][j] = v.w;
        }
        __syncthreads();

#pragma unroll 4
        for (int k = 0; k < 32; k++) {
            float a[8], b[8];
            const float4* ap = (const float4*)(&As[k][ti * 8]);
            ((float4*)a)[0] = ap[0];
            ((float4*)a)[1] = ap[1];
            const float4* bq = (const float4*)(&Bs[k][tj * 8]);
            ((float4*)b)[0] = bq[0];
            ((float4*)b)[1] = bq[1];
#pragma unroll
            for (int u = 0; u < 8; u++)
#pragma unroll
                for (int v = 0; v < 8; v++)
                    acc[u][v] = fmaf(a[u], b[v], acc[u][v]);
        }
        __syncthreads();
    }

    float mx = -INFINITY;
#pragma unroll
    for (int u = 0; u < 8; u++)
#pragma unroll
        for (int v = 0; v < 8; v++) mx = fmaxf(mx, acc[u][v]);
#pragma unroll
    for (int o = 16; o; o >>= 1) mx = fmaxf(mx, __shfl_xor_sync(0xffffffffu, mx, o));
    __shared__ float wred[8];
    if (tj == 0) wred[ti] = mx;
    __syncthreads();
    if (tid == 0) {
        float r = wred[0];
#pragma unroll
        for (int i = 1; i < 8; i++) r = fmaxf(r, wred[i]);
        g_mv[q * PB + p] = r;
    }
}

// ---------------------------------------------------------------------------
// Final loss: 16 warps, one per q-row of 128 entries (4 per lane).
// NOTE: reference overwrites loss_mulvec1 with the KLD term; CE(mv) is dead.
// ---------------------------------------------------------------------------
__global__ void loss_kernel(float* __restrict__ out) {
    int tid = threadIdx.x;  // 512
    int w = tid >> 5;       // q row
    int lane = tid & 31;
    const float* sr = g_scores + w * PB;
    const float* mr = g_mv + w * PB;
    float s[4], m[4], si[4];
#pragma unroll
    for (int c = 0; c < 4; c++) {
        int j = lane + 32 * c;
        s[c] = sr[j];
        m[c] = mr[j];
        si[c] = s[c] + 0.3f * m[c];  // W1=1.0, W3=0.3, TEMPERATURE=1.0
    }
    float mxs = -INFINITY, mxm = -INFINITY, mxi = -INFINITY;
#pragma unroll
    for (int c = 0; c < 4; c++) {
        mxs = fmaxf(mxs, s[c]);
        mxm = fmaxf(mxm, m[c]);
        mxi = fmaxf(mxi, si[c]);
    }
#pragma unroll
    for (int o = 16; o; o >>= 1) {
        mxs = fmaxf(mxs, __shfl_xor_sync(0xffffffffu, mxs, o));
        mxm = fmaxf(mxm, __shfl_xor_sync(0xffffffffu, mxm, o));
        mxi = fmaxf(mxi, __shfl_xor_sync(0xffffffffu, mxi, o));
    }
    float es = 0.f, em = 0.f, ei = 0.f;
#pragma unroll
    for (int c = 0; c < 4; c++) {
        es += expf(s[c] - mxs);
        em += expf(m[c] - mxm);
        ei += expf(si[c] - mxi);
    }
#pragma unroll
    for (int o = 16; o; o >>= 1) {
        es += __shfl_xor_sync(0xffffffffu, es, o);
        em += __shfl_xor_sync(0xffffffffu, em, o);
        ei += __shfl_xor_sync(0xffffffffu, ei, o);
    }
    float lse_s = mxs + logf(es);
    float lse_m = mxm + logf(em);
    float lse_i = mxi + logf(ei);

    // KLD terms: target = log_softmax(s_inter), inputs = log_softmax(scores/mv)
    float k1 = 0.f, k2 = 0.f;
#pragma unroll
    for (int c = 0; c < 4; c++) {
        float t = si[c] - lse_i;
        float pb = expf(t);
        k1 += pb * (t - (s[c] - lse_s));
        k2 += pb * (t - (m[c] - lse_m));
    }
#pragma unroll
    for (int o = 16; o; o >>= 1) {
        k1 += __shfl_xor_sync(0xffffffffu, k1, o);
        k2 += __shfl_xor_sync(0xffffffffu, k2, o);
    }

    __shared__ float sm[16][4];
    if (lane == 0) {
        int tgt = w * 8;  // group_size = 128/16
        float ce_s = lse_s - sr[tgt];
        float ce_i = lse_i - (sr[tgt] + 0.3f * mr[tgt]);
        sm[w][0] = ce_s;
        sm[w][1] = ce_i;
        sm[w][2] = k1;
        sm[w][3] = k2;
    }
    __syncthreads();
    if (tid == 0) {
        float ce_s = 0.f, ce_i = 0.f, k1s = 0.f, k2s = 0.f;
#pragma unroll
        for (int i = 0; i < 16; i++) {
            ce_s += sm[i][0];
            ce_i += sm[i][1];
            k1s += sm[i][2];
            k2s += sm[i][3];
        }
        ce_s *= (1.0f / 16.0f);
        ce_i *= (1.0f / 16.0f);
        k1s *= (1.0f / 16.0f);
        k2s *= (1.0f / 16.0f);
        // loss_dense1=ce_s, loss_inter=ce_i, loss_dense2=k1s, loss_mulvec1=k2s
        float L1 = 0.3f * (ce_s + k2s + ce_i);
        float L2 = 0.2f * (k1s + k2s);
        out[0] = 0.5f * (L1 + L2);
    }
}

// ---------------------------------------------------------------------------
extern "C" void kernel_launch(void* const* d_in, const int* in_sizes, int n_in,
                              void* d_out, int out_size) {
    const float* qh = (const float*)d_in[0];
    const float* ph = (const float*)d_in[1];
    // Defensive: q_hidden has 16*64*768 = 786432 elems, p_hidden 25165824.
    if (n_in >= 2 && in_sizes[0] > in_sizes[1]) {
        const float* t = qh; qh = ph; ph = t;
    }

    norm_q_kernel<<<QN * IN, 256>>>(qh);
    norm_p_kernel<<<PB * JN, 256>>>(ph);
    scores_kernel<<<QN, PB>>>(qh, ph);
    mv_kernel<<<dim3(PB, QN), 256>>>();
    loss_kernel<<<1, 512>>>((float*)d_out);
}

// round 2
// speedup vs baseline: 1.0019x; 1.0019x over previous
#include <cuda_runtime.h>
#include <math.h>

#define QN 16
#define IN 64
#define PB 128
#define JN 256
#define DN 768

// Scratch (device globals: no allocation, allowed by harness rules)
__device__ float g_qn[QN * IN * DN];        // ~3 MB normalized q
__device__ float g_pn[PB * JN * DN];        // ~100 MB normalized p
__device__ float g_scores[QN * PB];
__device__ float g_mv[QN * PB];

// ---------------------------------------------------------------------------
// Row L2-normalize: one block per row of 768, 256 threads
// ---------------------------------------------------------------------------
__device__ __forceinline__ void normalize_row(const float* __restrict__ xr,
                                              float* __restrict__ yr) {
    int tid = threadIdx.x;
    float v0 = xr[tid], v1 = xr[tid + 256], v2 = xr[tid + 512];
    float ss = v0 * v0 + v1 * v1 + v2 * v2;
#pragma unroll
    for (int o = 16; o; o >>= 1) ss += __shfl_xor_sync(0xffffffffu, ss, o);
    __shared__ float red[8];
    __shared__ float inv;
    if ((tid & 31) == 0) red[tid >> 5] = ss;
    __syncthreads();
    if (tid == 0) {
        float t = 0.f;
#pragma unroll
        for (int i = 0; i < 8; i++) t += red[i];
        float n = sqrtf(t);
        inv = 1.0f / fmaxf(n, 1e-12f);
    }
    __syncthreads();
    float iv = inv;
    yr[tid] = v0 * iv;
    yr[tid + 256] = v1 * iv;
    yr[tid + 512] = v2 * iv;
}

__global__ void norm_q_kernel(const float* __restrict__ x) {
    size_t row = blockIdx.x;
    normalize_row(x + row * DN, g_qn + row * DN);
}

__global__ void norm_p_kernel(const float* __restrict__ x) {
    size_t row = blockIdx.x;
    normalize_row(x + row * DN, g_pn + row * DN);
}

// ---------------------------------------------------------------------------
// scores[q][p] = dot(q_hidden[q,0,:], p_hidden[p,0,:])
// ---------------------------------------------------------------------------
__global__ void scores_kernel(const float* __restrict__ qh,
                              const float* __restrict__ ph) {
    int q = blockIdx.x;
    int p = threadIdx.x;  // 128 threads
    __shared__ float qs[DN];
    for (int k = p; k < DN; k += PB) qs[k] = qh[(size_t)q * IN * DN + k];
    __syncthreads();
    const float* pr = ph + (size_t)p * JN * DN;  // row j=0 of page p
    float s = 0.f;
    for (int k = 0; k < DN; k++) s = fmaf(qs[k], pr[k], s);
    g_scores[q * PB + p] = s;
}

// ---------------------------------------------------------------------------
// mv_scores[q][p] = max_{i,j} qn[q,i,:] . pn[p,j,:]
// Register-blocked GEMM tile 64(i) x 256(j), K=768, 8x8 microtile per thread.
// ---------------------------------------------------------------------------
__global__ __launch_bounds__(256) void mv_kernel() {
    const int p = blockIdx.x;
    const int q = blockIdx.y;
    __shared__ float As[32][68];    // [k][i], padded (stride%4==0 for float4)
    __shared__ float Bs[32][260];   // [k][j], padded

    const float* Aq = g_qn + (size_t)q * IN * DN;
    const float* Bp = g_pn + (size_t)p * JN * DN;
    const int tid = threadIdx.x;
    const int ti = tid >> 5;   // warp id -> i block (8 rows)
    const int tj = tid & 31;   // lane -> j block (8 cols)

    float acc[8][8];
#pragma unroll
    for (int u = 0; u < 8; u++)
#pragma unroll
        for (int v = 0; v < 8; v++) acc[u][v] = 0.f;

    for (int k0 = 0; k0 < DN; k0 += 32) {
        // A chunk: 64 rows x 32 k = 512 float4, 2 per thread (transpose store)
#pragma unroll
        for (int r = 0; r < 2; r++) {
            int idx = tid * 2 + r;
            int i = idx >> 3;
            int kq = (idx & 7) << 2;
            float4 v = *(const float4*)(Aq + (size_t)i * DN + k0 + kq);
            As[kq + 0][i] = v.x;
            As[kq + 1][i] = v.y;
            As[kq + 2][i] = v.z;
            As[kq + 3][i] = v.w;
        }
        // B chunk: 256 rows x 32 k = 2048 float4, 8 per thread
#pragma unroll
        for (int r = 0; r < 8; r++) {
            int idx = tid + 256 * r;
            int j = idx >> 3;
            int kq = (idx & 7) << 2;
            float4 v = *(const float4*)(Bp + (size_t)j * DN + k0 + kq);
            Bs[kq + 0][j] = v.x;
            Bs[kq + 1][j] = v.y;
            Bs[kq + 2][j] = v.z;
            Bs[kq + 3][j] = v.w;
        }
        __syncthreads();

#pragma unroll 4
        for (int k = 0; k < 32; k++) {
            float a[8], b[8];
            const float4* ap = (const float4*)(&As[k][ti * 8]);
            ((float4*)a)[0] = ap[0];
            ((float4*)a)[1] = ap[1];
            const float4* bq = (const float4*)(&Bs[k][tj * 8]);
            ((float4*)b)[0] = bq[0];
            ((float4*)b)[1] = bq[1];
#pragma unroll
            for (int u = 0; u < 8; u++)
#pragma unroll
                for (int v = 0; v < 8; v++)
                    acc[u][v] = fmaf(a[u], b[v], acc[u][v]);
        }
        __syncthreads();
    }

    float mx = -INFINITY;
#pragma unroll
    for (int u = 0; u < 8; u++)
#pragma unroll
        for (int v = 0; v < 8; v++) mx = fmaxf(mx, acc[u][v]);
#pragma unroll
    for (int o = 16; o; o >>= 1) mx = fmaxf(mx, __shfl_xor_sync(0xffffffffu, mx, o));
    __shared__ float wred[8];
    if (tj == 0) wred[ti] = mx;
    __syncthreads();
    if (tid == 0) {
        float r = wred[0];
#pragma unroll
        for (int i = 1; i < 8; i++) r = fmaxf(r, wred[i]);
        g_mv[q * PB + p] = r;
    }
}

// ---------------------------------------------------------------------------
// Final loss: 16 warps, one per q-row of 128 entries (4 per lane).
// NOTE: reference overwrites loss_mulvec1 with the KLD term; CE(mv) is dead.
// ---------------------------------------------------------------------------
__global__ void loss_kernel(float* __restrict__ out) {
    int tid = threadIdx.x;  // 512
    int w = tid >> 5;       // q row
    int lane = tid & 31;
    const float* sr = g_scores + w * PB;
    const float* mr = g_mv + w * PB;
    float s[4], m[4], si[4];
#pragma unroll
    for (int c = 0; c < 4; c++) {
        int j = lane + 32 * c;
        s[c] = sr[j];
        m[c] = mr[j];
        si[c] = s[c] + 0.3f * m[c];  // W1=1.0, W3=0.3, TEMPERATURE=1.0
    }
    float mxs = -INFINITY, mxm = -INFINITY, mxi = -INFINITY;
#pragma unroll
    for (int c = 0; c < 4; c++) {
        mxs = fmaxf(mxs, s[c]);
        mxm = fmaxf(mxm, m[c]);
        mxi = fmaxf(mxi, si[c]);
    }
#pragma unroll
    for (int o = 16; o; o >>= 1) {
        mxs = fmaxf(mxs, __shfl_xor_sync(0xffffffffu, mxs, o));
        mxm = fmaxf(mxm, __shfl_xor_sync(0xffffffffu, mxm, o));
        mxi = fmaxf(mxi, __shfl_xor_sync(0xffffffffu, mxi, o));
    }
    float es = 0.f, em = 0.f, ei = 0.f;
#pragma unroll
    for (int c = 0; c < 4; c++) {
        es += expf(s[c] - mxs);
        em += expf(m[c] - mxm);
        ei += expf(si[c] - mxi);
    }
#pragma unroll
    for (int o = 16; o; o >>= 1) {
        es += __shfl_xor_sync(0xffffffffu, es, o);
        em += __shfl_xor_sync(0xffffffffu, em, o);
        ei += __shfl_xor_sync(0xffffffffu, ei, o);
    }
    float lse_s = mxs + logf(es);
    float lse_m = mxm + logf(em);
    float lse_i = mxi + logf(ei);

    // KLD terms: target = log_softmax(s_inter), inputs = log_softmax(scores/mv)
    float k1 = 0.f, k2 = 0.f;
#pragma unroll
    for (int c = 0; c < 4; c++) {
        float t = si[c] - lse_i;
        float pb = expf(t);
        k1 += pb * (t - (s[c] - lse_s));
        k2 += pb * (t - (m[c] - lse_m));
    }
#pragma unroll
    for (int o = 16; o; o >>= 1) {
        k1 += __shfl_xor_sync(0xffffffffu, k1, o);
        k2 += __shfl_xor_sync(0xffffffffu, k2, o);
    }

    __shared__ float sm[16][4];
    if (lane == 0) {
        int tgt = w * 8;  // group_size = 128/16
        float ce_s = lse_s - sr[tgt];
        float ce_i = lse_i - (sr[tgt] + 0.3f * mr[tgt]);
        sm[w][0] = ce_s;
        sm[w][1] = ce_i;
        sm[w][2] = k1;
        sm[w][3] = k2;
    }
    __syncthreads();
    if (tid == 0) {
        float ce_s = 0.f, ce_i = 0.f, k1s = 0.f, k2s = 0.f;
#pragma unroll
        for (int i = 0; i < 16; i++) {
            ce_s += sm[i][0];
            ce_i += sm[i][1];
            k1s += sm[i][2];
            k2s += sm[i][3];
        }
        ce_s *= (1.0f / 16.0f);
        ce_i *= (1.0f / 16.0f);
        k1s *= (1.0f / 16.0f);
        k2s *= (1.0f / 16.0f);
        // loss_dense1=ce_s, loss_inter=ce_i, loss_dense2=k1s, loss_mulvec1=k2s
        float L1 = 0.3f * (ce_s + k2s + ce_i);
        float L2 = 0.2f * (k1s + k2s);
        out[0] = 0.5f * (L1 + L2);
    }
}

// ---------------------------------------------------------------------------
extern "C" void kernel_launch(void* const* d_in, const int* in_sizes, int n_in,
                              void* d_out, int out_size) {
    const float* qh = (const float*)d_in[0];
    const float* ph = (const float*)d_in[1];
    // Defensive: q_hidden has 16*64*768 = 786432 elems, p_hidden 25165824.
    if (n_in >= 2 && in_sizes[0] > in_sizes[1]) {
        const float* t = qh; qh = ph; ph = t;
    }

    norm_q_kernel<<<QN * IN, 256>>>(qh);
    norm_p_kernel<<<PB * JN, 256>>>(ph);
    scores_kernel<<<QN, PB>>>(qh, ph);
    mv_kernel<<<dim3(PB, QN), 256>>>();
    loss_kernel<<<1, 512>>>((float*)d_out);
}